// round 1
// baseline (speedup 1.0000x reference)
#include <cuda_runtime.h>
#include <cuda_bf16.h>
#include <math.h>

// Problem constants
#define BATCH 2
#define SEQ 2048
#define DIM 2048
#define NUM_HEADS 16
#define HEAD_DIM 128
#define QKV_OUT (3 * NUM_HEADS * HEAD_DIM)   // 6144
#define M_TOKENS (BATCH * SEQ)               // 4096

// Scratch (allocation-free rule: __device__ globals)
__device__ float g_qkv[(size_t)M_TOKENS * QKV_OUT];            // [B*S, 6144]
__device__ float g_comb[(size_t)M_TOKENS * (NUM_HEADS * HEAD_DIM)]; // [B*S, 2048]

// ---------------------------------------------------------------------------
// Tiled SGEMM:  C[m,n] = sum_k A[m,k] * B[n,k]   (both row-major, K contiguous)
// BM=BN=128, BK=16, 256 threads, 8x8 register microtile per thread.
// All dims here are multiples of the tile sizes (4096/6144/2048), no bounds checks.
// ---------------------------------------------------------------------------
#define GBM 128
#define GBN 128
#define GBK 16

__global__ __launch_bounds__(256, 2)
void sgemm_nt(const float* __restrict__ A, const float* __restrict__ B,
              float* __restrict__ C, int M, int N, int K) {
    __shared__ float As[GBK * GBM];   // transposed: As[k][m]
    __shared__ float Bs[GBK * GBN];   // transposed: Bs[k][n]

    const int bm = blockIdx.y * GBM;
    const int bn = blockIdx.x * GBN;
    const int tid = threadIdx.x;
    const int tx = tid & 15;          // 0..15
    const int ty = tid >> 4;          // 0..15

    float acc[8][8];
#pragma unroll
    for (int i = 0; i < 8; i++)
#pragma unroll
        for (int j = 0; j < 8; j++) acc[i][j] = 0.0f;

    for (int k0 = 0; k0 < K; k0 += GBK) {
        // Load A tile (128x16) and B tile (128x16), 512 float4 each, 2 per thread.
#pragma unroll
        for (int it = 0; it < 2; it++) {
            int idx = tid + it * 256;     // 0..511
            int row = idx >> 2;           // 0..127
            int c4  = idx & 3;            // 0..3
            float4 va = *(const float4*)(A + (size_t)(bm + row) * K + k0 + c4 * 4);
            As[(c4 * 4 + 0) * GBM + row] = va.x;
            As[(c4 * 4 + 1) * GBM + row] = va.y;
            As[(c4 * 4 + 2) * GBM + row] = va.z;
            As[(c4 * 4 + 3) * GBM + row] = va.w;
            float4 vb = *(const float4*)(B + (size_t)(bn + row) * K + k0 + c4 * 4);
            Bs[(c4 * 4 + 0) * GBN + row] = vb.x;
            Bs[(c4 * 4 + 1) * GBN + row] = vb.y;
            Bs[(c4 * 4 + 2) * GBN + row] = vb.z;
            Bs[(c4 * 4 + 3) * GBN + row] = vb.w;
        }
        __syncthreads();

#pragma unroll
        for (int k = 0; k < GBK; k++) {
            float a[8], b[8];
            *(float4*)(a)     = *(const float4*)(As + k * GBM + ty * 8);
            *(float4*)(a + 4) = *(const float4*)(As + k * GBM + ty * 8 + 4);
            *(float4*)(b)     = *(const float4*)(Bs + k * GBN + tx * 8);
            *(float4*)(b + 4) = *(const float4*)(Bs + k * GBN + tx * 8 + 4);
#pragma unroll
            for (int i = 0; i < 8; i++)
#pragma unroll
                for (int j = 0; j < 8; j++)
                    acc[i][j] += a[i] * b[j];
        }
        __syncthreads();
    }

#pragma unroll
    for (int i = 0; i < 8; i++) {
        float* crow = C + (size_t)(bm + ty * 8 + i) * N + bn + tx * 8;
        float4 v0 = make_float4(acc[i][0], acc[i][1], acc[i][2], acc[i][3]);
        float4 v1 = make_float4(acc[i][4], acc[i][5], acc[i][6], acc[i][7]);
        *(float4*)(crow)     = v0;
        *(float4*)(crow + 4) = v1;
    }
}

// ---------------------------------------------------------------------------
// Flash-style attention, fp32.
// grid = (S/64, NUM_HEADS, BATCH), block = 256 threads.
// Each block: 64 query rows of one (b,h). KV streamed in 64-row tiles with
// online softmax. Output accumulators in registers (32 floats / thread).
// ---------------------------------------------------------------------------
#define BQ 64
#define BKV 64
#define QK_PITCH 132     // 128 + 4 pad: keeps float4 alignment, spreads banks
#define S_PITCH 65

// shared floats: Qs + Ks (64*132 each) + Vs (64*128) + Ssh (64*65)
#define ATTN_SMEM_FLOATS (BQ * QK_PITCH + BKV * QK_PITCH + BKV * HEAD_DIM + BQ * S_PITCH)
#define ATTN_SMEM_BYTES (ATTN_SMEM_FLOATS * 4)

__global__ __launch_bounds__(256, 1)
void attn_kernel(const float* __restrict__ qkv, float* __restrict__ comb) {
    extern __shared__ float sm[];
    float* Qs  = sm;                               // [64][132]
    float* Ks  = Qs + BQ * QK_PITCH;               // [64][132]
    float* Vs  = Ks + BKV * QK_PITCH;              // [64][128]
    float* Ssh = Vs + BKV * HEAD_DIM;              // [64][65]

    const int qtile = blockIdx.x;
    const int h = blockIdx.y;
    const int b = blockIdx.z;
    const int tid = threadIdx.x;
    const float scale = 0.08838834764831845f;      // 1/sqrt(128)

    const int q0 = qtile * BQ;
    const float* qbase = qkv + (size_t)(b * SEQ) * QKV_OUT + h * HEAD_DIM;
    const float* kbase = qkv + (size_t)(b * SEQ) * QKV_OUT + (NUM_HEADS + h) * HEAD_DIM;
    const float* vbase = qkv + (size_t)(b * SEQ) * QKV_OUT + (2 * NUM_HEADS + h) * HEAD_DIM;

    // Load Q tile: 64 rows x 128 = 2048 float4, 8 per thread.
    for (int i = tid; i < BQ * 32; i += 256) {
        int r = i >> 5, c4 = i & 31;
        float4 v = *(const float4*)(qbase + (size_t)(q0 + r) * QKV_OUT + c4 * 4);
        float* dst = Qs + r * QK_PITCH + c4 * 4;
        dst[0] = v.x; dst[1] = v.y; dst[2] = v.z; dst[3] = v.w;
    }

    // Softmax/PV ownership: 4 threads per query row, 32 head-dims each.
    const int r  = tid >> 2;        // query row 0..63
    const int g  = tid & 3;         // 0..3
    const int d0 = g * 32;
    // Score ownership: 16x16 thread grid, 4x4 microtile of the 64x64 scores.
    const int tx = tid & 15;
    const int ty = tid >> 4;

    float m = -1e30f, l = 0.0f;
    float acc[32];
#pragma unroll
    for (int j = 0; j < 32; j++) acc[j] = 0.0f;

    for (int k0 = 0; k0 < SEQ; k0 += BKV) {
        // Load K tile.
        for (int i = tid; i < BKV * 32; i += 256) {
            int rr = i >> 5, c4 = i & 31;
            float4 v = *(const float4*)(kbase + (size_t)(k0 + rr) * QKV_OUT + c4 * 4);
            float* dst = Ks + rr * QK_PITCH + c4 * 4;
            dst[0] = v.x; dst[1] = v.y; dst[2] = v.z; dst[3] = v.w;
        }
        __syncthreads();   // K (and on iter 0, Q) visible; prior-iter Ssh reads done

        // Scores: S[qi][kj] = scale * sum_d Q[qi][d] * K[kj][d]
        float sc[4][4];
#pragma unroll
        for (int a = 0; a < 4; a++)
#pragma unroll
            for (int bb = 0; bb < 4; bb++) sc[a][bb] = 0.0f;

        for (int d = 0; d < HEAD_DIM; d += 4) {
            float4 qv[4], kv[4];
#pragma unroll
            for (int a = 0; a < 4; a++)
                qv[a] = *(const float4*)(Qs + (ty + 16 * a) * QK_PITCH + d);
#pragma unroll
            for (int bb = 0; bb < 4; bb++)
                kv[bb] = *(const float4*)(Ks + (tx + 16 * bb) * QK_PITCH + d);
#pragma unroll
            for (int a = 0; a < 4; a++)
#pragma unroll
                for (int bb = 0; bb < 4; bb++) {
                    sc[a][bb] += qv[a].x * kv[bb].x;
                    sc[a][bb] += qv[a].y * kv[bb].y;
                    sc[a][bb] += qv[a].z * kv[bb].z;
                    sc[a][bb] += qv[a].w * kv[bb].w;
                }
        }
#pragma unroll
        for (int a = 0; a < 4; a++)
#pragma unroll
            for (int bb = 0; bb < 4; bb++)
                Ssh[(ty + 16 * a) * S_PITCH + (tx + 16 * bb)] = sc[a][bb] * scale;
        __syncthreads();   // scores visible

        // Load V tile (Ks no longer needed; Vs is a separate buffer).
        for (int i = tid; i < BKV * 32; i += 256) {
            int rr = i >> 5, c4 = i & 31;
            float4 v = *(const float4*)(vbase + (size_t)(k0 + rr) * QKV_OUT + c4 * 4);
            float* dst = Vs + rr * HEAD_DIM + c4 * 4;
            dst[0] = v.x; dst[1] = v.y; dst[2] = v.z; dst[3] = v.w;
        }

        // Row max (each of the 4 row-threads scans the full row — redundant but simple).
        float tmax = -1e30f;
        for (int j = 0; j < BKV; j++) tmax = fmaxf(tmax, Ssh[r * S_PITCH + j]);
        float mnew = fmaxf(m, tmax);
        float corr = __expf(m - mnew);
        __syncthreads();   // all row-max scans done before in-place exp overwrite

        // exp in place (disjoint j per g-thread).
        for (int j = g; j < BKV; j += 4)
            Ssh[r * S_PITCH + j] = __expf(Ssh[r * S_PITCH + j] - mnew);
        __syncthreads();   // p visible + V tile loaded

        float rowsum = 0.0f;
        for (int j = 0; j < BKV; j++) rowsum += Ssh[r * S_PITCH + j];
        l = l * corr + rowsum;
        m = mnew;

#pragma unroll
        for (int j = 0; j < 32; j++) acc[j] *= corr;

        for (int kk = 0; kk < BKV; kk++) {
            float p = Ssh[r * S_PITCH + kk];
            const float4* vr = (const float4*)(Vs + kk * HEAD_DIM + d0);
#pragma unroll
            for (int j4 = 0; j4 < 8; j4++) {
                float4 v = vr[j4];
                acc[j4 * 4 + 0] += p * v.x;
                acc[j4 * 4 + 1] += p * v.y;
                acc[j4 * 4 + 2] += p * v.z;
                acc[j4 * 4 + 3] += p * v.w;
            }
        }
        __syncthreads();   // PV reads of Ssh/Vs done before next-iter overwrite
    }

    float inv = 1.0f / l;
    float* out = comb + (size_t)(b * SEQ + q0 + r) * (NUM_HEADS * HEAD_DIM)
               + h * HEAD_DIM + d0;
#pragma unroll
    for (int j4 = 0; j4 < 8; j4++) {
        float4 v = make_float4(acc[j4 * 4 + 0] * inv, acc[j4 * 4 + 1] * inv,
                               acc[j4 * 4 + 2] * inv, acc[j4 * 4 + 3] * inv);
        *(float4*)(out + j4 * 4) = v;
    }
}

// ---------------------------------------------------------------------------
// Launch
// ---------------------------------------------------------------------------
extern "C" void kernel_launch(void* const* d_in, const int* in_sizes, int n_in,
                              void* d_out, int out_size) {
    const float* x     = (const float*)d_in[0];   // [B,S,DIM]
    const float* w_qkv = (const float*)d_in[1];   // [6144, 2048]
    const float* w_out = (const float*)d_in[2];   // [2048, 2048]
    float* out = (float*)d_out;                   // [B,S,2048]

    float *qkv, *comb;
    cudaGetSymbolAddress((void**)&qkv, g_qkv);
    cudaGetSymbolAddress((void**)&comb, g_comb);

    // 1) QKV projection: [4096,2048] @ [6144,2048]^T -> [4096,6144]
    {
        dim3 grid(QKV_OUT / GBN, M_TOKENS / GBM);   // (48, 32)
        sgemm_nt<<<grid, 256>>>(x, w_qkv, qkv, M_TOKENS, QKV_OUT, DIM);
    }

    // 2) Attention
    {
        cudaFuncSetAttribute(attn_kernel,
                             cudaFuncAttributeMaxDynamicSharedMemorySize,
                             ATTN_SMEM_BYTES);
        dim3 grid(SEQ / BQ, NUM_HEADS, BATCH);      // (32, 16, 2)
        attn_kernel<<<grid, 256, ATTN_SMEM_BYTES>>>(qkv, comb);
    }

    // 3) Output projection: [4096,2048] @ [2048,2048]^T -> [4096,2048]
    {
        dim3 grid(DIM / GBN, M_TOKENS / GBM);       // (16, 32)
        sgemm_nt<<<grid, 256>>>(comb, w_out, out, M_TOKENS, DIM,
                                NUM_HEADS * HEAD_DIM);
    }
}

// round 2
// speedup vs baseline: 2.2855x; 2.2855x over previous
#include <cuda_runtime.h>
#include <cuda_bf16.h>
#include <math.h>

// Problem constants
#define BATCH 2
#define SEQ 2048
#define DIM 2048
#define NUM_HEADS 16
#define HEAD_DIM 128
#define QKV_OUT (3 * NUM_HEADS * HEAD_DIM)   // 6144
#define M_TOKENS (BATCH * SEQ)               // 4096

// Scratch (allocation-free rule: __device__ globals)
__device__ float g_qkv[(size_t)M_TOKENS * QKV_OUT];            // [B*S, 6144]
__device__ float g_comb[(size_t)M_TOKENS * (NUM_HEADS * HEAD_DIM)]; // [B*S, 2048]

// ---------------------------------------------------------------------------
// Tiled SGEMM:  C[m,n] = sum_k A[m,k] * B[n,k]   (both row-major, K contiguous)
// BM=BN=128, BK=16, 256 threads, 8x8 register microtile per thread.
// ---------------------------------------------------------------------------
#define GBM 128
#define GBN 128
#define GBK 16

__global__ __launch_bounds__(256, 2)
void sgemm_nt(const float* __restrict__ A, const float* __restrict__ B,
              float* __restrict__ C, int M, int N, int K) {
    __shared__ float As[GBK * GBM];   // transposed: As[k][m]
    __shared__ float Bs[GBK * GBN];   // transposed: Bs[k][n]

    const int bm = blockIdx.y * GBM;
    const int bn = blockIdx.x * GBN;
    const int tid = threadIdx.x;
    const int tx = tid & 15;          // 0..15
    const int ty = tid >> 4;          // 0..15

    float acc[8][8];
#pragma unroll
    for (int i = 0; i < 8; i++)
#pragma unroll
        for (int j = 0; j < 8; j++) acc[i][j] = 0.0f;

    for (int k0 = 0; k0 < K; k0 += GBK) {
#pragma unroll
        for (int it = 0; it < 2; it++) {
            int idx = tid + it * 256;     // 0..511
            int row = idx >> 2;           // 0..127
            int c4  = idx & 3;            // 0..3
            float4 va = *(const float4*)(A + (size_t)(bm + row) * K + k0 + c4 * 4);
            As[(c4 * 4 + 0) * GBM + row] = va.x;
            As[(c4 * 4 + 1) * GBM + row] = va.y;
            As[(c4 * 4 + 2) * GBM + row] = va.z;
            As[(c4 * 4 + 3) * GBM + row] = va.w;
            float4 vb = *(const float4*)(B + (size_t)(bn + row) * K + k0 + c4 * 4);
            Bs[(c4 * 4 + 0) * GBN + row] = vb.x;
            Bs[(c4 * 4 + 1) * GBN + row] = vb.y;
            Bs[(c4 * 4 + 2) * GBN + row] = vb.z;
            Bs[(c4 * 4 + 3) * GBN + row] = vb.w;
        }
        __syncthreads();

#pragma unroll
        for (int k = 0; k < GBK; k++) {
            float a[8], b[8];
            *(float4*)(a)     = *(const float4*)(As + k * GBM + ty * 8);
            *(float4*)(a + 4) = *(const float4*)(As + k * GBM + ty * 8 + 4);
            *(float4*)(b)     = *(const float4*)(Bs + k * GBN + tx * 8);
            *(float4*)(b + 4) = *(const float4*)(Bs + k * GBN + tx * 8 + 4);
#pragma unroll
            for (int i = 0; i < 8; i++)
#pragma unroll
                for (int j = 0; j < 8; j++)
                    acc[i][j] += a[i] * b[j];
        }
        __syncthreads();
    }

#pragma unroll
    for (int i = 0; i < 8; i++) {
        float* crow = C + (size_t)(bm + ty * 8 + i) * N + bn + tx * 8;
        *(float4*)(crow)     = make_float4(acc[i][0], acc[i][1], acc[i][2], acc[i][3]);
        *(float4*)(crow + 4) = make_float4(acc[i][4], acc[i][5], acc[i][6], acc[i][7]);
    }
}

// ---------------------------------------------------------------------------
// Flash-style attention v2, fp32.
// grid = (S/64, NUM_HEADS, BATCH), block = 256 threads, occupancy 2.
// Changes vs v1:
//  - K and V share one smem buffer (85 KB total -> 2 blocks/SM)
//  - warp-shuffle softmax (4 lanes per row, register-resident chunk of 16)
//  - PV is a 4x8 register-microtile GEMM (2.7 flop/smem-float vs 1.0)
//  - 4 barriers/tile instead of 6 (incl. the implicit redundant-scan ones)
// ---------------------------------------------------------------------------
#define BQ 64
#define BKV 64
#define PITCH 132        // 128 + 4: float4-aligned, de-conflicts row-strided reads
#define S_PITCH 68       // 64 + 4

// shared floats: Qs + KVs + Ssh + corr_s + l_s
#define ATTN_SMEM_FLOATS (BQ * PITCH + BKV * PITCH + BQ * S_PITCH + 2 * BQ)
#define ATTN_SMEM_BYTES (ATTN_SMEM_FLOATS * 4)

__global__ __launch_bounds__(256, 2)
void attn_kernel(const float* __restrict__ qkv, float* __restrict__ comb) {
    extern __shared__ float sm[];
    float* Qs     = sm;                              // [64][132]
    float* KVs    = Qs + BQ * PITCH;                 // [64][132]  K, then V
    float* Ssh    = KVs + BKV * PITCH;               // [64][68]
    float* corr_s = Ssh + BQ * S_PITCH;              // [64]
    float* l_s    = corr_s + BQ;                     // [64]

    const int qtile = blockIdx.x;
    const int h = blockIdx.y;
    const int b = blockIdx.z;
    const int tid = threadIdx.x;
    const float scale = 0.08838834764831845f;        // 1/sqrt(128)

    const int tx = tid & 15;     // QK: score col group; PV: d col group
    const int ty = tid >> 4;     // QK: score row group; PV: q row group
    const int r  = tid >> 2;     // softmax: owned row
    const int g  = tid & 3;      // softmax: 16-col chunk index

    const int q0 = qtile * BQ;
    const float* qbase = qkv + (size_t)(b * SEQ) * QKV_OUT + h * HEAD_DIM;
    const float* kbase = qkv + (size_t)(b * SEQ) * QKV_OUT + (NUM_HEADS + h) * HEAD_DIM;
    const float* vbase = qkv + (size_t)(b * SEQ) * QKV_OUT + (2 * NUM_HEADS + h) * HEAD_DIM;

    // Load Q tile: 64 rows x 128 floats, coalesced (32 threads per row).
    for (int i = tid; i < BQ * 32; i += 256) {
        int rr = i >> 5, c4 = i & 31;
        float4 v = *(const float4*)(qbase + (size_t)(q0 + rr) * QKV_OUT + c4 * 4);
        float* dst = Qs + rr * PITCH + c4 * 4;
        dst[0] = v.x; dst[1] = v.y; dst[2] = v.z; dst[3] = v.w;
    }

    float m = -1e30f, l = 0.0f;
    // PV accumulators: rows 4*ty+i (i<4), cols 8*tx+j (j<8)
    float acc[32];
#pragma unroll
    for (int j = 0; j < 32; j++) acc[j] = 0.0f;

    for (int k0 = 0; k0 < SEQ; k0 += BKV) {
        // ---- load K into KVs (prev iter's PV reads guarded by loop-end barrier)
        for (int i = tid; i < BKV * 32; i += 256) {
            int rr = i >> 5, c4 = i & 31;
            float4 v = *(const float4*)(kbase + (size_t)(k0 + rr) * QKV_OUT + c4 * 4);
            float* dst = KVs + rr * PITCH + c4 * 4;
            dst[0] = v.x; dst[1] = v.y; dst[2] = v.z; dst[3] = v.w;
        }
        __syncthreads();   // (1) Q (iter 0) + K visible

        // ---- scores: 4x4 microtile, rows ty+16a, cols tx+16b
        float sc[4][4];
#pragma unroll
        for (int a = 0; a < 4; a++)
#pragma unroll
            for (int bb = 0; bb < 4; bb++) sc[a][bb] = 0.0f;

#pragma unroll 4
        for (int d = 0; d < HEAD_DIM; d += 4) {
            float4 qv[4], kv[4];
#pragma unroll
            for (int a = 0; a < 4; a++)
                qv[a] = *(const float4*)(Qs + (ty + 16 * a) * PITCH + d);
#pragma unroll
            for (int bb = 0; bb < 4; bb++)
                kv[bb] = *(const float4*)(KVs + (tx + 16 * bb) * PITCH + d);
#pragma unroll
            for (int a = 0; a < 4; a++)
#pragma unroll
                for (int bb = 0; bb < 4; bb++) {
                    sc[a][bb] += qv[a].x * kv[bb].x;
                    sc[a][bb] += qv[a].y * kv[bb].y;
                    sc[a][bb] += qv[a].z * kv[bb].z;
                    sc[a][bb] += qv[a].w * kv[bb].w;
                }
        }
#pragma unroll
        for (int a = 0; a < 4; a++)
#pragma unroll
            for (int bb = 0; bb < 4; bb++)
                Ssh[(ty + 16 * a) * S_PITCH + (tx + 16 * bb)] = sc[a][bb] * scale;
        __syncthreads();   // (2) scores visible; all K reads done -> KVs reusable

        // ---- load V into KVs (overwrites K)
        for (int i = tid; i < BKV * 32; i += 256) {
            int rr = i >> 5, c4 = i & 31;
            float4 v = *(const float4*)(vbase + (size_t)(k0 + rr) * QKV_OUT + c4 * 4);
            float* dst = KVs + rr * PITCH + c4 * 4;
            dst[0] = v.x; dst[1] = v.y; dst[2] = v.z; dst[3] = v.w;
        }

        // ---- online softmax: 4 lanes per row (lanes 4r+g, shuffle partners 1,2)
        {
            float sv[16];
            float vmax = -1e30f;
            const float* srow = Ssh + r * S_PITCH + g * 16;
#pragma unroll
            for (int j4 = 0; j4 < 4; j4++) {
                float4 v = *(const float4*)(srow + j4 * 4);
                sv[j4 * 4 + 0] = v.x; sv[j4 * 4 + 1] = v.y;
                sv[j4 * 4 + 2] = v.z; sv[j4 * 4 + 3] = v.w;
                vmax = fmaxf(vmax, fmaxf(fmaxf(v.x, v.y), fmaxf(v.z, v.w)));
            }
            vmax = fmaxf(vmax, __shfl_xor_sync(0xffffffffu, vmax, 1));
            vmax = fmaxf(vmax, __shfl_xor_sync(0xffffffffu, vmax, 2));
            float mnew = fmaxf(m, vmax);
            float corr = __expf(m - mnew);
            m = mnew;
            float s = 0.0f;
#pragma unroll
            for (int j = 0; j < 16; j++) {
                float e = __expf(sv[j] - mnew);
                sv[j] = e;
                s += e;
            }
            float* wrow = Ssh + r * S_PITCH + g * 16;
#pragma unroll
            for (int j4 = 0; j4 < 4; j4++)
                *(float4*)(wrow + j4 * 4) =
                    make_float4(sv[j4 * 4], sv[j4 * 4 + 1], sv[j4 * 4 + 2], sv[j4 * 4 + 3]);
            s += __shfl_xor_sync(0xffffffffu, s, 1);
            s += __shfl_xor_sync(0xffffffffu, s, 2);
            l = l * corr + s;
            if (g == 0) corr_s[r] = corr;
        }
        __syncthreads();   // (3) exp(P) + V + corr_s visible

        // ---- PV: acc[i][j] += sum_kk P[4ty+i][kk] * V[kk][8tx+j]
        {
            float c4r[4];
#pragma unroll
            for (int i = 0; i < 4; i++) c4r[i] = corr_s[4 * ty + i];
#pragma unroll
            for (int i = 0; i < 4; i++)
#pragma unroll
                for (int j = 0; j < 8; j++) acc[i * 8 + j] *= c4r[i];

#pragma unroll 8
            for (int kk = 0; kk < BKV; kk++) {
                float p[4];
#pragma unroll
                for (int i = 0; i < 4; i++)
                    p[i] = Ssh[(4 * ty + i) * S_PITCH + kk];
                float4 v0 = *(const float4*)(KVs + kk * PITCH + 8 * tx);
                float4 v1 = *(const float4*)(KVs + kk * PITCH + 8 * tx + 4);
#pragma unroll
                for (int i = 0; i < 4; i++) {
                    acc[i * 8 + 0] += p[i] * v0.x;
                    acc[i * 8 + 1] += p[i] * v0.y;
                    acc[i * 8 + 2] += p[i] * v0.z;
                    acc[i * 8 + 3] += p[i] * v0.w;
                    acc[i * 8 + 4] += p[i] * v1.x;
                    acc[i * 8 + 5] += p[i] * v1.y;
                    acc[i * 8 + 6] += p[i] * v1.z;
                    acc[i * 8 + 7] += p[i] * v1.w;
                }
            }
        }
        __syncthreads();   // (4) PV reads done -> KVs/Ssh reusable next tile
    }

    // publish row sums, then normalize + store
    if (g == 0) l_s[r] = l;
    __syncthreads();

#pragma unroll
    for (int i = 0; i < 4; i++) {
        float inv = 1.0f / l_s[4 * ty + i];
        float* out = comb + (size_t)(b * SEQ + q0 + 4 * ty + i) * (NUM_HEADS * HEAD_DIM)
                   + h * HEAD_DIM + 8 * tx;
        *(float4*)(out)     = make_float4(acc[i * 8 + 0] * inv, acc[i * 8 + 1] * inv,
                                          acc[i * 8 + 2] * inv, acc[i * 8 + 3] * inv);
        *(float4*)(out + 4) = make_float4(acc[i * 8 + 4] * inv, acc[i * 8 + 5] * inv,
                                          acc[i * 8 + 6] * inv, acc[i * 8 + 7] * inv);
    }
}

// ---------------------------------------------------------------------------
// Launch
// ---------------------------------------------------------------------------
extern "C" void kernel_launch(void* const* d_in, const int* in_sizes, int n_in,
                              void* d_out, int out_size) {
    const float* x     = (const float*)d_in[0];   // [B,S,DIM]
    const float* w_qkv = (const float*)d_in[1];   // [6144, 2048]
    const float* w_out = (const float*)d_in[2];   // [2048, 2048]
    float* out = (float*)d_out;                   // [B,S,2048]

    float *qkv, *comb;
    cudaGetSymbolAddress((void**)&qkv, g_qkv);
    cudaGetSymbolAddress((void**)&comb, g_comb);

    // 1) QKV projection: [4096,2048] @ [6144,2048]^T -> [4096,6144]
    {
        dim3 grid(QKV_OUT / GBN, M_TOKENS / GBM);   // (48, 32)
        sgemm_nt<<<grid, 256>>>(x, w_qkv, qkv, M_TOKENS, QKV_OUT, DIM);
    }

    // 2) Attention
    {
        cudaFuncSetAttribute(attn_kernel,
                             cudaFuncAttributeMaxDynamicSharedMemorySize,
                             ATTN_SMEM_BYTES);
        dim3 grid(SEQ / BQ, NUM_HEADS, BATCH);      // (32, 16, 2)
        attn_kernel<<<grid, 256, ATTN_SMEM_BYTES>>>(qkv, comb);
    }

    // 3) Output projection: [4096,2048] @ [2048,2048]^T -> [4096,2048]
    {
        dim3 grid(DIM / GBN, M_TOKENS / GBM);       // (16, 32)
        sgemm_nt<<<grid, 256>>>(comb, w_out, out, M_TOKENS, DIM,
                                NUM_HEADS * HEAD_DIM);
    }
}